// round 5
// baseline (speedup 1.0000x reference)
#include <cuda_runtime.h>
#include <math.h>

#define B_ 256
#define N_ 4096
#define D_ 128
#define C_ 32
#define HB (B_ / 2)      // 128 b per half-kernel
#define SPLIT2 2         // within a half, each n handled by 2 warps (64 b each)
#define NCHUNK 16        // n-dimension split for the yhat partial kernel

// Scratch (allocation-free rule: __device__ globals)
__device__ float g_partial[NCHUNK][B_][C_];  // partial y_hat accumulations
__device__ float g_psum[NCHUNK][B_];         // partial row sums of activations

// ---------------------------------------------------------------------------
// Main kernel over one b-half [bbase, bbase+HB). One warp owns (n, 64-b span).
// Case row + weights computed once into registers; streams 512B delta writes.
// ---------------------------------------------------------------------------
__global__ void __launch_bounds__(256) main_half_kernel(const float* __restrict__ q,
                                                        const float* __restrict__ cases,
                                                        const float* __restrict__ fw,
                                                        const float* __restrict__ dwt,
                                                        const float* __restrict__ bias,
                                                        float* __restrict__ delta,
                                                        float* __restrict__ act,
                                                        int bbase)
{
    int gw   = (blockIdx.x * blockDim.x + threadIdx.x) >> 5;  // global warp id
    int lane = threadIdx.x & 31;
    int n    = gw & (N_ - 1);        // consecutive warps -> consecutive n
    int sub  = gw >> 12;             // 0 or 1 within this half

    // Register-resident per-n data: cases row, softplus(fw), wf = sp * -|dw|
    const float4* c4p = reinterpret_cast<const float4*>(cases + (size_t)n * D_);
    const float4* f4p = reinterpret_cast<const float4*>(fw    + (size_t)n * D_);
    const float4* w4p = reinterpret_cast<const float4*>(dwt   + (size_t)n * D_);
    float4 c4 = __ldg(c4p + lane);
    float4 fr = __ldg(f4p + lane);
    float4 dr = __ldg(w4p + lane);
    float  bn = __ldg(bias + n);

    float4 f4;
    f4.x = (fr.x > 20.0f) ? fr.x : log1pf(expf(fr.x));
    f4.y = (fr.y > 20.0f) ? fr.y : log1pf(expf(fr.y));
    f4.z = (fr.z > 20.0f) ? fr.z : log1pf(expf(fr.z));
    f4.w = (fr.w > 20.0f) ? fr.w : log1pf(expf(fr.w));

    float4 w4;
    w4.x = f4.x * (-fabsf(dr.x));
    w4.y = f4.y * (-fabsf(dr.y));
    w4.z = f4.z * (-fabsf(dr.z));
    w4.w = f4.w * (-fabsf(dr.w));

    const int b0 = bbase + sub * (HB / SPLIT2);
    const int b1 = b0 + (HB / SPLIT2);

    const float4* q4base = reinterpret_cast<const float4*>(q);
    float4*       d4base = reinterpret_cast<float4*>(delta);

    for (int b = b0; b < b1; b++) {
        float4 q4 = __ldg(q4base + (size_t)b * (D_ / 4) + lane);

        float dx = q4.x - c4.x;
        float dy = q4.y - c4.y;
        float dz = q4.z - c4.z;
        float dwv = q4.w - c4.w;
        dx *= dx; dy *= dy; dz *= dz; dwv *= dwv;

        float4 o;
        o.x = dx * f4.x; o.y = dy * f4.y; o.z = dz * f4.z; o.w = dwv * f4.w;

        float a = dx * w4.x;
        a = fmaf(dy,  w4.y, a);
        a = fmaf(dz,  w4.z, a);
        a = fmaf(dwv, w4.w, a);

        // streaming store — evict-first (delta never re-read)
        __stcs(&d4base[((size_t)b * N_ + n) * (D_ / 4) + lane], o);

        a += __shfl_xor_sync(0xffffffffu, a, 16);
        a += __shfl_xor_sync(0xffffffffu, a, 8);
        a += __shfl_xor_sync(0xffffffffu, a, 4);
        a += __shfl_xor_sync(0xffffffffu, a, 2);
        a += __shfl_xor_sync(0xffffffffu, a, 1);

        if (lane == 0) {
            float s  = a + bn;
            float av = 1.0f / (1.0f + expf(-s));
            act[(size_t)b * N_ + n] = av;   // stays L2-resident for epilogue
        }
    }
}

// ---------------------------------------------------------------------------
// yhat partials for one b-half: 16 b-groups x NCHUNK chunks = 256 blocks.
// Each block: 8 b rows x (N_/NCHUNK) n's. Warp w owns 4 c-columns.
// ---------------------------------------------------------------------------
__global__ void __launch_bounds__(256) yhat_partial_kernel(const float* __restrict__ act,
                                                           const float* __restrict__ targets,
                                                           int bbase)
{
    int chunk = blockIdx.x & (NCHUNK - 1);
    int bg    = blockIdx.x >> 4;            // 0..15
    int b0    = bbase + bg * 8;
    int w     = threadIdx.x >> 5;
    int lane  = threadIdx.x & 31;
    int c0    = w * 4;

    const int nper = N_ / NCHUNK;           // 256
    const int nst  = chunk * nper;

    float acc[8][4];
    float srow[8];
    #pragma unroll
    for (int i = 0; i < 8; i++) {
        srow[i] = 0.0f;
        #pragma unroll
        for (int j = 0; j < 4; j++) acc[i][j] = 0.0f;
    }

    #pragma unroll
    for (int it = 0; it < nper / 32; it++) {
        int n = nst + it * 32 + lane;
        float4 t = __ldg(reinterpret_cast<const float4*>(targets + (size_t)n * C_ + c0));
        #pragma unroll
        for (int i = 0; i < 8; i++) {
            float a = __ldg(act + (size_t)(b0 + i) * N_ + n);
            srow[i] += a;
            acc[i][0] = fmaf(a, t.x, acc[i][0]);
            acc[i][1] = fmaf(a, t.y, acc[i][1]);
            acc[i][2] = fmaf(a, t.z, acc[i][2]);
            acc[i][3] = fmaf(a, t.w, acc[i][3]);
        }
    }

    #pragma unroll
    for (int i = 0; i < 8; i++) {
        #pragma unroll
        for (int j = 0; j < 4; j++) {
            float v = acc[i][j];
            v += __shfl_xor_sync(0xffffffffu, v, 16);
            v += __shfl_xor_sync(0xffffffffu, v, 8);
            v += __shfl_xor_sync(0xffffffffu, v, 4);
            v += __shfl_xor_sync(0xffffffffu, v, 2);
            v += __shfl_xor_sync(0xffffffffu, v, 1);
            acc[i][j] = v;
        }
        float s = srow[i];
        s += __shfl_xor_sync(0xffffffffu, s, 16);
        s += __shfl_xor_sync(0xffffffffu, s, 8);
        s += __shfl_xor_sync(0xffffffffu, s, 4);
        s += __shfl_xor_sync(0xffffffffu, s, 2);
        s += __shfl_xor_sync(0xffffffffu, s, 1);
        srow[i] = s;
    }

    if (lane == 0) {
        #pragma unroll
        for (int i = 0; i < 8; i++) {
            #pragma unroll
            for (int j = 0; j < 4; j++)
                g_partial[chunk][b0 + i][c0 + j] = acc[i][j];
            if (w == 0) g_psum[chunk][b0 + i] = srow[i];
        }
    }
}

// ---------------------------------------------------------------------------
// Final reduce for one b-half: one thread per (b, c); 16-way sums (L2-hot).
// ---------------------------------------------------------------------------
__global__ void __launch_bounds__(256) yhat_reduce_kernel(float* __restrict__ yhat,
                                                          int bbase)
{
    int idx = blockIdx.x * blockDim.x + threadIdx.x;   // 0 .. HB*C_-1
    int b = bbase + (idx >> 5);
    int c = idx & (C_ - 1);

    float v = 0.0f, s = 0.0f;
    #pragma unroll
    for (int k = 0; k < NCHUNK; k++) {
        v += g_partial[k][b][c];
        s += g_psum[k][b];
    }
    yhat[(size_t)b * C_ + c] = v / (s + 0.01f);
}

// ---------------------------------------------------------------------------
// Launch: fork-join graph.
//   stream0: main(h0) -> main(h1) -> epi(h1) -> [wait epi(h0)]
//   stream1:        \-> epi(h0)  (overlaps main(h1))
// ---------------------------------------------------------------------------
extern "C" void kernel_launch(void* const* d_in, const int* in_sizes, int n_in,
                              void* d_out, int out_size)
{
    const float* queries = (const float*)d_in[0];
    const float* cases   = (const float*)d_in[1];
    const float* targets = (const float*)d_in[2];
    const float* fw      = (const float*)d_in[3];
    const float* dw      = (const float*)d_in[4];
    const float* bias    = (const float*)d_in[5];

    float* out   = (float*)d_out;
    float* yhat  = out;                                   // B*C
    float* act   = out + (size_t)B_ * C_;                 // B*N
    float* delta = out + (size_t)B_ * C_ + (size_t)B_ * N_;

    static cudaStream_t s1 = nullptr;
    static cudaEvent_t  ev_m0 = nullptr, ev_e0 = nullptr;
    if (s1 == nullptr) {
        cudaStreamCreateWithFlags(&s1, cudaStreamNonBlocking);
        cudaEventCreateWithFlags(&ev_m0, cudaEventDisableTiming);
        cudaEventCreateWithFlags(&ev_e0, cudaEventDisableTiming);
    }

    const int main_blocks = (N_ * SPLIT2) / 8;   // 1024 CTAs per half
    const int epi_blocks  = (HB / 8) * NCHUNK;   // 256 CTAs per half
    const int red_blocks  = (HB * C_) / 256;     // 16 CTAs per half

    // half 0 main on the capture (default) stream
    main_half_kernel<<<main_blocks, 256>>>(queries, cases, fw, dw, bias, delta, act, 0);
    cudaEventRecord(ev_m0, 0);

    // half 0 epilogue on side stream, overlapping half-1 main
    cudaStreamWaitEvent(s1, ev_m0, 0);
    yhat_partial_kernel<<<epi_blocks, 256, 0, s1>>>(act, targets, 0);
    yhat_reduce_kernel<<<red_blocks, 256, 0, s1>>>(yhat, 0);
    cudaEventRecord(ev_e0, s1);

    // half 1 main + epilogue on default stream
    main_half_kernel<<<main_blocks, 256>>>(queries, cases, fw, dw, bias, delta, act, HB);
    yhat_partial_kernel<<<epi_blocks, 256>>>(act, targets, HB);
    yhat_reduce_kernel<<<red_blocks, 256>>>(yhat, HB);

    // join: downstream harness work must see half-0 epilogue results
    cudaStreamWaitEvent(0, ev_e0, 0);
}

// round 6
// speedup vs baseline: 1.0074x; 1.0074x over previous
#include <cuda_runtime.h>
#include <math.h>

#define B_ 256
#define N_ 4096
#define D_ 128
#define C_ 32
#define HN (N_ / 2)      // 2048 n per half-kernel
#define BSPLIT 2         // each n handled by 2 warps, each covering B/2 batches
#define NCHUNK 16        // total n-chunks for the yhat partial kernels
#define HCHUNK (NCHUNK / 2)

// Scratch (allocation-free rule: __device__ globals)
__device__ float g_partial[NCHUNK][B_][C_];  // partial y_hat accumulations
__device__ float g_psum[NCHUNK][B_];         // partial row sums of activations

// ---------------------------------------------------------------------------
// Main kernel over one n-half [nbase, nbase+HN). One warp owns (n, b-half),
// identical per-warp shape to the proven R3 kernel: 128-iter b-loop,
// register-resident case row, streaming 512B delta writes.
// ---------------------------------------------------------------------------
__global__ void __launch_bounds__(256) main_nhalf_kernel(const float* __restrict__ q,
                                                         const float* __restrict__ cases,
                                                         const float* __restrict__ fw,
                                                         const float* __restrict__ dwt,
                                                         const float* __restrict__ bias,
                                                         float* __restrict__ delta,
                                                         float* __restrict__ act,
                                                         int nbase)
{
    int gw   = (blockIdx.x * blockDim.x + threadIdx.x) >> 5;  // 0 .. HN*BSPLIT-1
    int lane = threadIdx.x & 31;
    int n    = nbase + (gw & (HN - 1));   // consecutive warps -> consecutive n
    int bh   = gw >> 11;                  // 0 or 1 (HN = 2048 -> 11 bits)

    // Register-resident per-n data: cases row, softplus(fw), wf = sp * -|dw|
    const float4* c4p = reinterpret_cast<const float4*>(cases + (size_t)n * D_);
    const float4* f4p = reinterpret_cast<const float4*>(fw    + (size_t)n * D_);
    const float4* w4p = reinterpret_cast<const float4*>(dwt   + (size_t)n * D_);
    float4 c4 = __ldg(c4p + lane);
    float4 fr = __ldg(f4p + lane);
    float4 dr = __ldg(w4p + lane);
    float  bn = __ldg(bias + n);

    float4 f4;
    f4.x = (fr.x > 20.0f) ? fr.x : log1pf(expf(fr.x));
    f4.y = (fr.y > 20.0f) ? fr.y : log1pf(expf(fr.y));
    f4.z = (fr.z > 20.0f) ? fr.z : log1pf(expf(fr.z));
    f4.w = (fr.w > 20.0f) ? fr.w : log1pf(expf(fr.w));

    float4 w4;
    w4.x = f4.x * (-fabsf(dr.x));
    w4.y = f4.y * (-fabsf(dr.y));
    w4.z = f4.z * (-fabsf(dr.z));
    w4.w = f4.w * (-fabsf(dr.w));

    const int b0 = bh * (B_ / BSPLIT);
    const int b1 = b0 + (B_ / BSPLIT);     // 128 iterations — do not shrink

    const float4* q4base = reinterpret_cast<const float4*>(q);
    float4*       d4base = reinterpret_cast<float4*>(delta);

    for (int b = b0; b < b1; b++) {
        float4 q4 = __ldg(q4base + (size_t)b * (D_ / 4) + lane);

        float dx = q4.x - c4.x;
        float dy = q4.y - c4.y;
        float dz = q4.z - c4.z;
        float dwv = q4.w - c4.w;
        dx *= dx; dy *= dy; dz *= dz; dwv *= dwv;

        float4 o;
        o.x = dx * f4.x; o.y = dy * f4.y; o.z = dz * f4.z; o.w = dwv * f4.w;

        float a = dx * w4.x;
        a = fmaf(dy,  w4.y, a);
        a = fmaf(dz,  w4.z, a);
        a = fmaf(dwv, w4.w, a);

        // streaming store — evict-first (delta never re-read)
        __stcs(&d4base[((size_t)b * N_ + n) * (D_ / 4) + lane], o);

        a += __shfl_xor_sync(0xffffffffu, a, 16);
        a += __shfl_xor_sync(0xffffffffu, a, 8);
        a += __shfl_xor_sync(0xffffffffu, a, 4);
        a += __shfl_xor_sync(0xffffffffu, a, 2);
        a += __shfl_xor_sync(0xffffffffu, a, 1);

        if (lane == 0) {
            float s  = a + bn;
            float av = 1.0f / (1.0f + expf(-s));
            act[(size_t)b * N_ + n] = av;
        }
    }
}

// ---------------------------------------------------------------------------
// yhat partials over one chunk-half: 32 b-groups x HCHUNK chunks = 256 blocks.
// Each block: 8 b rows x (N_/NCHUNK) n's. Warp w owns 4 c-columns.
// ---------------------------------------------------------------------------
__global__ void __launch_bounds__(256) yhat_partial_kernel(const float* __restrict__ act,
                                                           const float* __restrict__ targets,
                                                           int chunkbase)
{
    int chunk = chunkbase + (blockIdx.x & (HCHUNK - 1));
    int bg    = blockIdx.x >> 3;            // 0..31
    int b0    = bg * 8;
    int w     = threadIdx.x >> 5;
    int lane  = threadIdx.x & 31;
    int c0    = w * 4;

    const int nper = N_ / NCHUNK;           // 256
    const int nst  = chunk * nper;

    float acc[8][4];
    float srow[8];
    #pragma unroll
    for (int i = 0; i < 8; i++) {
        srow[i] = 0.0f;
        #pragma unroll
        for (int j = 0; j < 4; j++) acc[i][j] = 0.0f;
    }

    #pragma unroll
    for (int it = 0; it < nper / 32; it++) {
        int n = nst + it * 32 + lane;
        float4 t = __ldg(reinterpret_cast<const float4*>(targets + (size_t)n * C_ + c0));
        #pragma unroll
        for (int i = 0; i < 8; i++) {
            float a = __ldg(act + (size_t)(b0 + i) * N_ + n);
            srow[i] += a;
            acc[i][0] = fmaf(a, t.x, acc[i][0]);
            acc[i][1] = fmaf(a, t.y, acc[i][1]);
            acc[i][2] = fmaf(a, t.z, acc[i][2]);
            acc[i][3] = fmaf(a, t.w, acc[i][3]);
        }
    }

    #pragma unroll
    for (int i = 0; i < 8; i++) {
        #pragma unroll
        for (int j = 0; j < 4; j++) {
            float v = acc[i][j];
            v += __shfl_xor_sync(0xffffffffu, v, 16);
            v += __shfl_xor_sync(0xffffffffu, v, 8);
            v += __shfl_xor_sync(0xffffffffu, v, 4);
            v += __shfl_xor_sync(0xffffffffu, v, 2);
            v += __shfl_xor_sync(0xffffffffu, v, 1);
            acc[i][j] = v;
        }
        float s = srow[i];
        s += __shfl_xor_sync(0xffffffffu, s, 16);
        s += __shfl_xor_sync(0xffffffffu, s, 8);
        s += __shfl_xor_sync(0xffffffffu, s, 4);
        s += __shfl_xor_sync(0xffffffffu, s, 2);
        s += __shfl_xor_sync(0xffffffffu, s, 1);
        srow[i] = s;
    }

    if (lane == 0) {
        #pragma unroll
        for (int i = 0; i < 8; i++) {
            #pragma unroll
            for (int j = 0; j < 4; j++)
                g_partial[chunk][b0 + i][c0 + j] = acc[i][j];
            if (w == 0) g_psum[chunk][b0 + i] = srow[i];
        }
    }
}

// ---------------------------------------------------------------------------
// Final reduce: one thread per (b, c); 16-way partial sums (L2-hot).
// ---------------------------------------------------------------------------
__global__ void __launch_bounds__(256) yhat_reduce_kernel(float* __restrict__ yhat)
{
    int idx = blockIdx.x * blockDim.x + threadIdx.x;   // 0 .. B_*C_-1
    int b = idx >> 5;
    int c = idx & (C_ - 1);

    float v = 0.0f, s = 0.0f;
    #pragma unroll
    for (int k = 0; k < NCHUNK; k++) {
        v += g_partial[k][b][c];
        s += g_psum[k][b];
    }
    yhat[idx] = v / (s + 0.01f);
}

// ---------------------------------------------------------------------------
// Launch graph:
//   s0: main(n-half0) -> main(n-half1) -> epi_partial(chunks 8..15) -> [wait evB] -> reduce
//   s1:        \-[evA]-> epi_partial(chunks 0..7) -[evB]
// ---------------------------------------------------------------------------
extern "C" void kernel_launch(void* const* d_in, const int* in_sizes, int n_in,
                              void* d_out, int out_size)
{
    const float* queries = (const float*)d_in[0];
    const float* cases   = (const float*)d_in[1];
    const float* targets = (const float*)d_in[2];
    const float* fw      = (const float*)d_in[3];
    const float* dw      = (const float*)d_in[4];
    const float* bias    = (const float*)d_in[5];

    float* out   = (float*)d_out;
    float* yhat  = out;                                   // B*C
    float* act   = out + (size_t)B_ * C_;                 // B*N
    float* delta = out + (size_t)B_ * C_ + (size_t)B_ * N_;

    static cudaStream_t s1 = nullptr;
    static cudaEvent_t  evA = nullptr, evB = nullptr;
    if (s1 == nullptr) {
        cudaStreamCreateWithFlags(&s1, cudaStreamNonBlocking);
        cudaEventCreateWithFlags(&evA, cudaEventDisableTiming);
        cudaEventCreateWithFlags(&evB, cudaEventDisableTiming);
    }

    const int main_blocks = (HN * BSPLIT) / 8;        // 512 CTAs per n-half
    const int epi_blocks  = (B_ / 8) * HCHUNK;        // 256 CTAs per chunk-half
    const int red_blocks  = (B_ * C_) / 256;          // 32 CTAs

    // n-half 0 main
    main_nhalf_kernel<<<main_blocks, 256>>>(queries, cases, fw, dw, bias, delta, act, 0);
    cudaEventRecord(evA, 0);

    // epilogue for chunks 0..7 on side stream (needs only act[:, 0:2048])
    cudaStreamWaitEvent(s1, evA, 0);
    yhat_partial_kernel<<<epi_blocks, 256, 0, s1>>>(act, targets, 0);
    cudaEventRecord(evB, s1);

    // n-half 1 main + epilogue chunks 8..15 + final reduce on default stream
    main_nhalf_kernel<<<main_blocks, 256>>>(queries, cases, fw, dw, bias, delta, act, HN);
    yhat_partial_kernel<<<epi_blocks, 256>>>(act, targets, HCHUNK);
    cudaStreamWaitEvent(0, evB, 0);
    yhat_reduce_kernel<<<red_blocks, 256>>>(yhat);
}

// round 7
// speedup vs baseline: 1.4021x; 1.3918x over previous
#include <cuda_runtime.h>
#include <math.h>

#define B_ 256
#define N_ 4096
#define D_ 128
#define C_ 32
#define BSPLIT 2     // each n handled by 2 warps, each covering B/2 batches
#define NCHUNK 32    // n-dimension split for the yhat partial kernel

// Scratch (allocation-free rule: __device__ globals)
__device__ float g_partial[NCHUNK][B_][C_];  // partial y_hat accumulations (1 MB)
__device__ float g_psum[NCHUNK][B_];         // partial row sums of activations

// ---------------------------------------------------------------------------
// Main kernel (byte-identical shape to R3 — proven fastest): one warp owns
// (n, b-half); 128-iter b-loop; register-resident case row; streaming 512B
// delta writes. 1024 CTAs = one full wave. DO NOT SPLIT THIS KERNEL.
// ---------------------------------------------------------------------------
__global__ void __launch_bounds__(256) main_kernel(const float* __restrict__ q,
                                                   const float* __restrict__ cases,
                                                   const float* __restrict__ fw,
                                                   const float* __restrict__ dwt,
                                                   const float* __restrict__ bias,
                                                   float* __restrict__ delta,
                                                   float* __restrict__ act)
{
    int gw   = (blockIdx.x * blockDim.x + threadIdx.x) >> 5;  // global warp id
    int lane = threadIdx.x & 31;
    int n    = gw & (N_ - 1);        // consecutive warps -> consecutive n
    int bh   = gw >> 12;             // 0 or 1
    if (bh >= BSPLIT) return;

    // Register-resident per-n data: cases row, softplus(fw), wf = sp * -|dw|
    const float4* c4p = reinterpret_cast<const float4*>(cases + (size_t)n * D_);
    const float4* f4p = reinterpret_cast<const float4*>(fw    + (size_t)n * D_);
    const float4* w4p = reinterpret_cast<const float4*>(dwt   + (size_t)n * D_);
    float4 c4 = __ldg(c4p + lane);
    float4 fr = __ldg(f4p + lane);
    float4 dr = __ldg(w4p + lane);
    float  bn = __ldg(bias + n);

    float4 f4;
    f4.x = (fr.x > 20.0f) ? fr.x : log1pf(expf(fr.x));
    f4.y = (fr.y > 20.0f) ? fr.y : log1pf(expf(fr.y));
    f4.z = (fr.z > 20.0f) ? fr.z : log1pf(expf(fr.z));
    f4.w = (fr.w > 20.0f) ? fr.w : log1pf(expf(fr.w));

    float4 w4;
    w4.x = f4.x * (-fabsf(dr.x));
    w4.y = f4.y * (-fabsf(dr.y));
    w4.z = f4.z * (-fabsf(dr.z));
    w4.w = f4.w * (-fabsf(dr.w));

    const int b0 = bh * (B_ / BSPLIT);
    const int b1 = b0 + (B_ / BSPLIT);   // 128 iterations — do not shrink

    const float4* q4base = reinterpret_cast<const float4*>(q);
    float4*       d4base = reinterpret_cast<float4*>(delta);

    for (int b = b0; b < b1; b++) {
        float4 q4 = __ldg(q4base + (size_t)b * (D_ / 4) + lane);

        float dx = q4.x - c4.x;
        float dy = q4.y - c4.y;
        float dz = q4.z - c4.z;
        float dwv = q4.w - c4.w;
        dx *= dx; dy *= dy; dz *= dz; dwv *= dwv;

        float4 o;
        o.x = dx * f4.x; o.y = dy * f4.y; o.z = dz * f4.z; o.w = dwv * f4.w;

        float a = dx * w4.x;
        a = fmaf(dy,  w4.y, a);
        a = fmaf(dz,  w4.z, a);
        a = fmaf(dwv, w4.w, a);

        // streaming store — evict-first (delta never re-read)
        __stcs(&d4base[((size_t)b * N_ + n) * (D_ / 4) + lane], o);

        a += __shfl_xor_sync(0xffffffffu, a, 16);
        a += __shfl_xor_sync(0xffffffffu, a, 8);
        a += __shfl_xor_sync(0xffffffffu, a, 4);
        a += __shfl_xor_sync(0xffffffffu, a, 2);
        a += __shfl_xor_sync(0xffffffffu, a, 1);

        if (lane == 0) {
            float s  = a + bn;
            float av = 1.0f / (1.0f + expf(-s));
            act[(size_t)b * N_ + n] = av;   // stays L2-resident for epilogue
        }
    }
}

// ---------------------------------------------------------------------------
// yhat partials: 32 b-groups x NCHUNK(=32) chunks = 1024 blocks (one full
// wave). Each block: 8 b rows x 128 n's (4 iterations). Warp w owns 4 c-cols.
// ---------------------------------------------------------------------------
__global__ void __launch_bounds__(256) yhat_partial_kernel(const float* __restrict__ act,
                                                           const float* __restrict__ targets)
{
    int chunk = blockIdx.x & (NCHUNK - 1);
    int bg    = blockIdx.x >> 5;            // 0..31
    int b0    = bg * 8;
    int w     = threadIdx.x >> 5;
    int lane  = threadIdx.x & 31;
    int c0    = w * 4;

    const int nper = N_ / NCHUNK;           // 128
    const int nst  = chunk * nper;

    float acc[8][4];
    float srow[8];
    #pragma unroll
    for (int i = 0; i < 8; i++) {
        srow[i] = 0.0f;
        #pragma unroll
        for (int j = 0; j < 4; j++) acc[i][j] = 0.0f;
    }

    #pragma unroll
    for (int it = 0; it < nper / 32; it++) {
        int n = nst + it * 32 + lane;
        float4 t = __ldg(reinterpret_cast<const float4*>(targets + (size_t)n * C_ + c0));
        #pragma unroll
        for (int i = 0; i < 8; i++) {
            float a = __ldg(act + (size_t)(b0 + i) * N_ + n);
            srow[i] += a;
            acc[i][0] = fmaf(a, t.x, acc[i][0]);
            acc[i][1] = fmaf(a, t.y, acc[i][1]);
            acc[i][2] = fmaf(a, t.z, acc[i][2]);
            acc[i][3] = fmaf(a, t.w, acc[i][3]);
        }
    }

    #pragma unroll
    for (int i = 0; i < 8; i++) {
        #pragma unroll
        for (int j = 0; j < 4; j++) {
            float v = acc[i][j];
            v += __shfl_xor_sync(0xffffffffu, v, 16);
            v += __shfl_xor_sync(0xffffffffu, v, 8);
            v += __shfl_xor_sync(0xffffffffu, v, 4);
            v += __shfl_xor_sync(0xffffffffu, v, 2);
            v += __shfl_xor_sync(0xffffffffu, v, 1);
            acc[i][j] = v;
        }
        float s = srow[i];
        s += __shfl_xor_sync(0xffffffffu, s, 16);
        s += __shfl_xor_sync(0xffffffffu, s, 8);
        s += __shfl_xor_sync(0xffffffffu, s, 4);
        s += __shfl_xor_sync(0xffffffffu, s, 2);
        s += __shfl_xor_sync(0xffffffffu, s, 1);
        srow[i] = s;
    }

    if (lane == 0) {
        #pragma unroll
        for (int i = 0; i < 8; i++) {
            #pragma unroll
            for (int j = 0; j < 4; j++)
                g_partial[chunk][b0 + i][c0 + j] = acc[i][j];
            if (w == 0) g_psum[chunk][b0 + i] = srow[i];
        }
    }
}

// ---------------------------------------------------------------------------
// Final reduce: one thread per (b, c); 32-way partial sums (all L2-hot).
// ---------------------------------------------------------------------------
__global__ void __launch_bounds__(256) yhat_reduce_kernel(float* __restrict__ yhat)
{
    int idx = blockIdx.x * blockDim.x + threadIdx.x;   // 0 .. B_*C_-1
    int b = idx >> 5;
    int c = idx & (C_ - 1);

    float v = 0.0f, s = 0.0f;
    #pragma unroll
    for (int k = 0; k < NCHUNK; k++) {
        v += g_partial[k][b][c];
        s += g_psum[k][b];
    }
    yhat[idx] = v / (s + 0.01f);
}

// ---------------------------------------------------------------------------
// Launch: single stream, three kernels (R3 structure — proven).
// ---------------------------------------------------------------------------
extern "C" void kernel_launch(void* const* d_in, const int* in_sizes, int n_in,
                              void* d_out, int out_size)
{
    const float* queries = (const float*)d_in[0];
    const float* cases   = (const float*)d_in[1];
    const float* targets = (const float*)d_in[2];
    const float* fw      = (const float*)d_in[3];
    const float* dw      = (const float*)d_in[4];
    const float* bias    = (const float*)d_in[5];

    float* out   = (float*)d_out;
    float* yhat  = out;                                   // B*C
    float* act   = out + (size_t)B_ * C_;                 // B*N
    float* delta = out + (size_t)B_ * C_ + (size_t)B_ * N_;

    int total_warps = N_ * BSPLIT;
    main_kernel<<<total_warps / 8, 256>>>(queries, cases, fw, dw, bias, delta, act);
    yhat_partial_kernel<<<(B_ / 8) * NCHUNK, 256>>>(act, targets);
    yhat_reduce_kernel<<<(B_ * C_) / 256, 256>>>(yhat);
}